// round 2
// baseline (speedup 1.0000x reference)
#include <cuda_runtime.h>
#include <cuda_bf16.h>

// NuclearLossFunc: loss = sum(x^2) / (B*C), x: (32,64,256,256) fp32
// = 134,217,728 elements = 512 MiB read. Pure HBM-bound reduction.
//
// Single kernel, last-block-done pattern:
//   - each block: grid-stride float4 squared-sum -> g_partials[bid]
//   - atomic ticket counter; last arriving block reduces all partials
//     in double (fixed tree over fixed array -> deterministic) and
//     writes float(sum / (B*C)). Counter reset for graph replay.

#define NBLOCKS 1184           // 148 SMs * 8 CTAs (2 waves at 512 thr)
#define NTHREADS 512

__device__ float        g_partials[NBLOCKS];
__device__ unsigned int g_count;   // zero-initialized at module load

__global__ __launch_bounds__(NTHREADS) void sqsum_fused_kernel(
    const float4* __restrict__ in, long long n4,
    float* __restrict__ out, float scale)
{
    const int lane = threadIdx.x & 31;
    const int wid  = threadIdx.x >> 5;
    __shared__ float  ws[NTHREADS / 32];
    __shared__ bool   s_is_last;

    // ---- pass 1: grid-stride squared sum, 2x unrolled for MLP ----
    float s0 = 0.f, s1 = 0.f, s2 = 0.f, s3 = 0.f;
    float t0 = 0.f, t1 = 0.f, t2 = 0.f, t3 = 0.f;

    long long idx    = (long long)blockIdx.x * blockDim.x + threadIdx.x;
    long long stride = (long long)gridDim.x * blockDim.x;

    long long i = idx;
    for (; i + stride < n4; i += 2 * stride) {
        float4 a = in[i];
        float4 b = in[i + stride];
        s0 = fmaf(a.x, a.x, s0);
        s1 = fmaf(a.y, a.y, s1);
        s2 = fmaf(a.z, a.z, s2);
        s3 = fmaf(a.w, a.w, s3);
        t0 = fmaf(b.x, b.x, t0);
        t1 = fmaf(b.y, b.y, t1);
        t2 = fmaf(b.z, b.z, t2);
        t3 = fmaf(b.w, b.w, t3);
    }
    if (i < n4) {
        float4 a = in[i];
        s0 = fmaf(a.x, a.x, s0);
        s1 = fmaf(a.y, a.y, s1);
        s2 = fmaf(a.z, a.z, s2);
        s3 = fmaf(a.w, a.w, s3);
    }
    float s = ((s0 + t0) + (s1 + t1)) + ((s2 + t2) + (s3 + t3));

    #pragma unroll
    for (int o = 16; o > 0; o >>= 1)
        s += __shfl_xor_sync(0xffffffffu, s, o);

    if (lane == 0) ws[wid] = s;
    __syncthreads();

    if (wid == 0) {
        s = (lane < NTHREADS / 32) ? ws[lane] : 0.f;
        #pragma unroll
        for (int o = 16; o > 0; o >>= 1)
            s += __shfl_xor_sync(0xffffffffu, s, o);
        if (lane == 0) g_partials[blockIdx.x] = s;
    }

    // ---- last-block election ----
    if (threadIdx.x == 0) {
        __threadfence();  // make g_partials[bid] visible before ticket
        unsigned int ticket = atomicAdd(&g_count, 1u);
        s_is_last = (ticket == (unsigned int)(gridDim.x - 1));
    }
    __syncthreads();
    if (!s_is_last) return;

    // ---- last block: reduce all partials in double (deterministic) ----
    __shared__ double wd[NTHREADS / 32];
    double d = 0.0;
    for (int p = threadIdx.x; p < NBLOCKS; p += NTHREADS)
        d += (double)g_partials[p];

    #pragma unroll
    for (int o = 16; o > 0; o >>= 1)
        d += __shfl_xor_sync(0xffffffffu, d, o);

    if (lane == 0) wd[wid] = d;
    __syncthreads();

    if (wid == 0) {
        d = (lane < NTHREADS / 32) ? wd[lane] : 0.0;
        #pragma unroll
        for (int o = 16; o > 0; o >>= 1)
            d += __shfl_xor_sync(0xffffffffu, d, o);
        if (lane == 0) {
            out[0] = (float)(d * (double)scale);
            g_count = 0;  // reset for next graph replay
        }
    }
}

extern "C" void kernel_launch(void* const* d_in, const int* in_sizes, int n_in,
                              void* d_out, int out_size)
{
    const float* x = (const float*)d_in[0];
    long long n = (long long)in_sizes[0];     // 134217728, divisible by 4
    long long n4 = n >> 2;

    // B*C = n / (256*256) = 2048
    float scale = 1.0f / (float)(n / (256LL * 256LL));

    sqsum_fused_kernel<<<NBLOCKS, NTHREADS>>>((const float4*)x, n4,
                                              (float*)d_out, scale);
}

// round 3
// speedup vs baseline: 1.0134x; 1.0134x over previous
#include <cuda_runtime.h>
#include <cuda_bf16.h>

// NuclearLossFunc: loss = sum(x^2) / (B*C), x: (32,64,256,256) fp32
// = 134,217,728 elements = 512 MiB read. Pure HBM-bound reduction.
//
// R3: R1's hot loop (measured 7.06 TB/s) + last-block-done finalize
// (removes the 6.8us second-kernel launch). Deterministic: ticket
// atomic carries no FP data; final reduce is a fixed tree in double.

#define NBLOCKS 1184           // 148 SMs * 8 CTAs
#define NTHREADS 512

__device__ float        g_partials[NBLOCKS];
__device__ unsigned int g_count;   // zero-initialized at module load

__global__ __launch_bounds__(NTHREADS) void sqsum_fused_kernel(
    const float4* __restrict__ in, long long n4,
    float* __restrict__ out, float scale)
{
    const int lane = threadIdx.x & 31;
    const int wid  = threadIdx.x >> 5;
    __shared__ float ws[NTHREADS / 32];
    __shared__ bool  s_is_last;

    // ---- hot loop: identical to R1 (measured ~88% of HBM spec) ----
    float s0 = 0.f, s1 = 0.f, s2 = 0.f, s3 = 0.f;
    long long idx    = (long long)blockIdx.x * blockDim.x + threadIdx.x;
    long long stride = (long long)gridDim.x * blockDim.x;

    for (long long i = idx; i < n4; i += stride) {
        float4 v = in[i];
        s0 = fmaf(v.x, v.x, s0);
        s1 = fmaf(v.y, v.y, s1);
        s2 = fmaf(v.z, v.z, s2);
        s3 = fmaf(v.w, v.w, s3);
    }
    float s = (s0 + s1) + (s2 + s3);

    #pragma unroll
    for (int o = 16; o > 0; o >>= 1)
        s += __shfl_xor_sync(0xffffffffu, s, o);

    if (lane == 0) ws[wid] = s;
    __syncthreads();

    if (wid == 0) {
        s = (lane < NTHREADS / 32) ? ws[lane] : 0.f;
        #pragma unroll
        for (int o = 16; o > 0; o >>= 1)
            s += __shfl_xor_sync(0xffffffffu, s, o);
        if (lane == 0) g_partials[blockIdx.x] = s;
    }

    // ---- last-block election ----
    if (threadIdx.x == 0) {
        __threadfence();  // publish g_partials[bid] before ticket
        unsigned int ticket = atomicAdd(&g_count, 1u);
        s_is_last = (ticket == (unsigned int)(gridDim.x - 1));
    }
    __syncthreads();
    if (!s_is_last) return;

    // ---- last block: reduce partials in double (deterministic) ----
    __shared__ double wd[NTHREADS / 32];
    double d = 0.0;
    for (int p = threadIdx.x; p < NBLOCKS; p += NTHREADS)
        d += (double)g_partials[p];

    #pragma unroll
    for (int o = 16; o > 0; o >>= 1)
        d += __shfl_xor_sync(0xffffffffu, d, o);

    if (lane == 0) wd[wid] = d;
    __syncthreads();

    if (wid == 0) {
        d = (lane < NTHREADS / 32) ? wd[lane] : 0.0;
        #pragma unroll
        for (int o = 16; o > 0; o >>= 1)
            d += __shfl_xor_sync(0xffffffffu, d, o);
        if (lane == 0) {
            out[0] = (float)(d * (double)scale);
            g_count = 0;  // reset for graph replay
        }
    }
}

extern "C" void kernel_launch(void* const* d_in, const int* in_sizes, int n_in,
                              void* d_out, int out_size)
{
    const float* x = (const float*)d_in[0];
    long long n = (long long)in_sizes[0];     // 134217728, divisible by 4
    long long n4 = n >> 2;

    // B*C = n / (256*256) = 2048
    float scale = 1.0f / (float)(n / (256LL * 256LL));

    sqsum_fused_kernel<<<NBLOCKS, NTHREADS>>>((const float4*)x, n4,
                                              (float*)d_out, scale);
}